// round 8
// baseline (speedup 1.0000x reference)
#include <cuda_runtime.h>
#include <cuda_bf16.h>
#include <cstdint>
#include <cstddef>

#define D_MODEL   1024
#define D_INNER   1024
#define NQK       32
#define NV_       32
#define DSTATE    64
#define DCONV     4
#define CHUNK_    128
#define CONV_DIM  5120
#define HEADDIM   32
#define IN_PROJ   6176
#define IN_PROJ_PAD 6272
#define BATCH     2
#define SEQ       8192
#define BT        16384
#define NC_       64

// ---- scratch (device globals) ----
__device__ __align__(16) float g_xbcza[(size_t)BT * IN_PROJ];
__device__ __align__(16) float g_xconv[(size_t)BT * CONV_DIM];
__device__ __align__(16) float g_y[(size_t)BT * D_INNER];
__device__ __align__(16) float g_states[(size_t)BATCH * NC_ * NV_ * HEADDIM * DSTATE];
__device__ __align__(16) float g_prevs [(size_t)BATCH * NC_ * NV_ * HEADDIM * DSTATE];
__device__ __align__(16) float g_acum  [(size_t)BATCH * NC_ * NV_ * CHUNK_];
__device__ __align__(16) float g_dc    [BATCH * NC_ * NV_];
__device__ __align__(16) __nv_bfloat16 g_act_hi[(size_t)BT * 1024];
__device__ __align__(16) __nv_bfloat16 g_act_lo[(size_t)BT * 1024];
__device__ __align__(16) __nv_bfloat16 g_w1_hi [(size_t)IN_PROJ_PAD * 1024];
__device__ __align__(16) __nv_bfloat16 g_w1_lo [(size_t)IN_PROJ_PAD * 1024];
__device__ __align__(16) __nv_bfloat16 g_w2_hi [(size_t)1024 * 1024];
__device__ __align__(16) __nv_bfloat16 g_w2_lo [(size_t)1024 * 1024];

// ---- packed f32x2 helpers (2x fp32 FMA throughput; PTX-only pattern) ----
__device__ __forceinline__ unsigned long long packf2(float lo, float hi) {
    unsigned long long r;
    asm("mov.b64 %0, {%1, %2};" : "=l"(r) : "f"(lo), "f"(hi));
    return r;
}
__device__ __forceinline__ unsigned long long ffma2(unsigned long long a,
                                                    unsigned long long b,
                                                    unsigned long long c) {
    unsigned long long d;
    asm("fma.rn.f32x2 %0, %1, %2, %3;" : "=l"(d) : "l"(a), "l"(b), "l"(c));
    return d;
}
__device__ __forceinline__ float2 unpackf2(unsigned long long v) {
    float lo, hi;
    asm("mov.b64 {%0, %1}, %2;" : "=f"(lo), "=f"(hi) : "l"(v));
    return make_float2(lo, hi);
}

// ===========================================================================
// split-bf16 conversion
// ===========================================================================
__global__ void cvt_split(const float* __restrict__ s,
                          __nv_bfloat16* __restrict__ hi,
                          __nv_bfloat16* __restrict__ lo,
                          int n_real, int n_total)
{
    int i = (blockIdx.x * 256 + threadIdx.x) * 4;
    if (i >= n_total) return;
    __nv_bfloat16 h[4], l[4];
    if (i < n_real) {
        float4 v = *(const float4*)(s + i);
        float a[4] = {v.x, v.y, v.z, v.w};
#pragma unroll
        for (int j = 0; j < 4; j++) {
            h[j] = __float2bfloat16(a[j]);
            l[j] = __float2bfloat16(a[j] - __bfloat162float(h[j]));
        }
    } else {
#pragma unroll
        for (int j = 0; j < 4; j++) { h[j] = __float2bfloat16(0.f); l[j] = h[j]; }
    }
    *(__nv_bfloat162*)(hi + i)     = __nv_bfloat162(h[0], h[1]);
    *(__nv_bfloat162*)(hi + i + 2) = __nv_bfloat162(h[2], h[3]);
    *(__nv_bfloat162*)(lo + i)     = __nv_bfloat162(l[0], l[1]);
    *(__nv_bfloat162*)(lo + i + 2) = __nv_bfloat162(l[2], l[3]);
}

// ===========================================================================
// HMMA split-bf16 GEMM (NT) with cp.async 2-stage pipeline. (unchanged R7)
// ===========================================================================
__device__ __forceinline__ uint32_t smem_u32(const void* p) {
    uint32_t a;
    asm("{ .reg .u64 t; cvta.to.shared.u64 t, %1; cvt.u32.u64 %0, t; }"
        : "=r"(a) : "l"(p));
    return a;
}
__device__ __forceinline__ uint32_t sw128(uint32_t off) {
    return off ^ ((off >> 3) & 0x70);
}
__device__ __forceinline__ void ldmat4(uint32_t& r0, uint32_t& r1,
                                       uint32_t& r2, uint32_t& r3, uint32_t a) {
    asm volatile("ldmatrix.sync.aligned.m8n8.x4.shared.b16 {%0,%1,%2,%3}, [%4];"
                 : "=r"(r0), "=r"(r1), "=r"(r2), "=r"(r3) : "r"(a));
}
__device__ __forceinline__ void mma16816(float* c, const uint32_t* a,
                                         uint32_t b0, uint32_t b1) {
    asm volatile(
        "mma.sync.aligned.m16n8k16.row.col.f32.bf16.bf16.f32 "
        "{%0,%1,%2,%3}, {%4,%5,%6,%7}, {%8,%9}, {%0,%1,%2,%3};"
        : "+f"(c[0]), "+f"(c[1]), "+f"(c[2]), "+f"(c[3])
        : "r"(a[0]), "r"(a[1]), "r"(a[2]), "r"(a[3]), "r"(b0), "r"(b1));
}
__device__ __forceinline__ void cp16(uint32_t dst, const void* src) {
    asm volatile("cp.async.cg.shared.global [%0], [%1], 16;"
                 :: "r"(dst), "l"(src));
}

__device__ __forceinline__ void load_tile_async(
    const __nv_bfloat16* __restrict__ g, int row0, int K, int k0,
    uint32_t sbase, int tid)
{
#pragma unroll
    for (int j = 0; j < 4; j++) {
        int u = tid + 256 * j;
        int row = u >> 3, cg = u & 7;
        uint32_t off = (uint32_t)(row * 128 + cg * 16);
        cp16(sbase + sw128(off), g + (size_t)(row0 + row) * K + k0 + cg * 8);
    }
}

#define STAGE_SZ 65536u
#define GEMM_SMEM (2 * 65536)
__global__ __launch_bounds__(256, 1)
void gemm_hmma(const __nv_bfloat16* __restrict__ Ahi,
               const __nv_bfloat16* __restrict__ Alo,
               const __nv_bfloat16* __restrict__ Bhi,
               const __nv_bfloat16* __restrict__ Blo,
               float* __restrict__ C, int K, int Nreal, int ldc)
{
    extern __shared__ char sm[];
    const uint32_t s0 = smem_u32(sm);
    const int tid = threadIdx.x;
    const int wid = tid >> 5, lid = tid & 31;
    const int wm = wid & 1, wn = wid >> 1;
    const int m0 = blockIdx.y * 128, n0 = blockIdx.x * 128;

    float acc[4][4][4];
#pragma unroll
    for (int i = 0; i < 4; i++)
#pragma unroll
        for (int j = 0; j < 4; j++)
#pragma unroll
            for (int q = 0; q < 4; q++) acc[i][j][q] = 0.f;

    const int lrow = lid & 15;
    const int lkb  = (lid >> 4) * 16;
    const int NKC = K >> 6;

    {
        uint32_t base = s0;
        load_tile_async(Ahi, m0, K, 0, base,             tid);
        load_tile_async(Alo, m0, K, 0, base + 16384,     tid);
        load_tile_async(Bhi, n0, K, 0, base + 32768,     tid);
        load_tile_async(Blo, n0, K, 0, base + 49152,     tid);
        asm volatile("cp.async.commit_group;");
    }

    for (int kc = 0; kc < NKC; kc++) {
        if (kc + 1 < NKC) {
            uint32_t base = s0 + ((kc + 1) & 1) * STAGE_SZ;
            int k0 = (kc + 1) << 6;
            load_tile_async(Ahi, m0, K, k0, base,         tid);
            load_tile_async(Alo, m0, K, k0, base + 16384, tid);
            load_tile_async(Bhi, n0, K, k0, base + 32768, tid);
            load_tile_async(Blo, n0, K, k0, base + 49152, tid);
            asm volatile("cp.async.commit_group;");
            asm volatile("cp.async.wait_group 1;");
        } else {
            asm volatile("cp.async.wait_group 0;");
        }
        __syncthreads();

        const uint32_t sAH = s0 + (kc & 1) * STAGE_SZ;
        const uint32_t sAL = sAH + 16384;
        const uint32_t sBH = sAH + 32768;
        const uint32_t sBL = sAH + 49152;
#pragma unroll
        for (int ks = 0; ks < 4; ks++) {
            const int kb = ks * 32 + lkb;
            uint32_t bh[2][4], bl[2][4];
#pragma unroll
            for (int g2 = 0; g2 < 2; g2++) {
                uint32_t off = (uint32_t)((wn * 32 + g2 * 16 + lrow) * 128 + kb);
                ldmat4(bh[g2][0], bh[g2][1], bh[g2][2], bh[g2][3], sBH + sw128(off));
                ldmat4(bl[g2][0], bl[g2][1], bl[g2][2], bl[g2][3], sBL + sw128(off));
            }
#pragma unroll
            for (int mi = 0; mi < 4; mi++) {
                uint32_t ah[4], al[4];
                uint32_t off = (uint32_t)((wm * 64 + mi * 16 + lrow) * 128 + kb);
                ldmat4(ah[0], ah[1], ah[2], ah[3], sAH + sw128(off));
                ldmat4(al[0], al[1], al[2], al[3], sAL + sw128(off));
#pragma unroll
                for (int ni = 0; ni < 4; ni++) {
                    const int g2 = ni >> 1, pt = ni & 1;
                    mma16816(acc[mi][ni], ah, bh[g2][pt], bh[g2][pt + 2]);
                    mma16816(acc[mi][ni], ah, bl[g2][pt], bl[g2][pt + 2]);
                    mma16816(acc[mi][ni], al, bh[g2][pt], bh[g2][pt + 2]);
                }
            }
        }
        __syncthreads();
    }

    const int crow = lid >> 2, ccol = (lid & 3) * 2;
#pragma unroll
    for (int mi = 0; mi < 4; mi++) {
#pragma unroll
        for (int ni = 0; ni < 4; ni++) {
            int n = n0 + wn * 32 + ni * 8 + ccol;
            if (n >= Nreal) continue;
            int m = m0 + wm * 64 + mi * 16 + crow;
            *(float2*)(C + (size_t)m * ldc + n) =
                make_float2(acc[mi][ni][0], acc[mi][ni][1]);
            *(float2*)(C + (size_t)(m + 8) * ldc + n) =
                make_float2(acc[mi][ni][2], acc[mi][ni][3]);
        }
    }
}

// ---------------------------------------------------------------------------
// Depthwise causal conv (4 taps) + bias — smem-tiled
// ---------------------------------------------------------------------------
#define CCH 64
#define CTT 64
__global__ __launch_bounds__(256) void conv_kernel(const float* __restrict__ cw,
                                                   const float* __restrict__ cb)
{
    __shared__ float s[(CTT + 3) * CCH];
    const int tid = threadIdx.x;
    const int c0 = blockIdx.x * CCH;
    const int tile = blockIdx.y;
    const int b = tile >> 7;
    const int t0 = (tile & 127) * CTT;
    const size_t row0 = (size_t)b * SEQ + t0;

    for (int e = tid; e < (CTT + 3) * CCH; e += 256) {
        int tl = e >> 6, c = e & 63;
        int t = t0 + tl - 3;
        float v = 0.f;
        if (t >= 0) v = g_xbcza[((size_t)b * SEQ + t) * IN_PROJ + c0 + c];
        s[e] = v;
    }
    __syncthreads();

    const int c = tid & 63, trow = tid >> 6;
    const int ch = c0 + c;
    const float w0 = cw[ch * 4 + 0], w1 = cw[ch * 4 + 1];
    const float w2 = cw[ch * 4 + 2], w3 = cw[ch * 4 + 3];
    const float bia = cb[ch];
#pragma unroll
    for (int j = 0; j < 16; j++) {
        int tl = trow + 4 * j;
        float acc = bia
            + w0 * s[(tl + 0) * CCH + c]
            + w1 * s[(tl + 1) * CCH + c]
            + w2 * s[(tl + 2) * CCH + c]
            + w3 * s[(tl + 3) * CCH + c];
        g_xconv[(row0 + tl) * CONV_DIM + ch] = acc;
    }
}

// ---------------------------------------------------------------------------
// Chunk kernel: per (h, c, b). dyn smem 153,088 B. f32x2 inner loops.
// ---------------------------------------------------------------------------
#define CTS 132
#define XSS 33
__global__ __launch_bounds__(256, 1) void chunk_kernel()
{
    extern __shared__ float smf[];
    float* Ct   = smf;
    float* Btm  = Ct + 64 * CTS;
    float* Xs   = Btm + 64 * CTS;
    float* Ps   = Xs + 128 * XSS;
    float* acum = Ps + 128 * CTS;
    float* darr = acum + CHUNK_;

    const int tid = threadIdx.x;
    const int h = blockIdx.x, c = blockIdx.y, b = blockIdx.z;
    const size_t bt0 = (size_t)b * SEQ + (size_t)c * CHUNK_;
    const int chunk_id = (b * NC_ + c) * NV_ + h;

    if (tid < 128) {
        float a = g_xbcza[(bt0 + tid) * IN_PROJ + (CONV_DIM + D_INNER) + h];
        darr[tid] = (a > 20.f) ? a : log1pf(expf(a));
    }
    __syncthreads();
    if (tid < 32) {
        float v0 = darr[tid*4+0], v1 = darr[tid*4+1];
        float v2 = darr[tid*4+2], v3 = darr[tid*4+3];
        float s1 = v0+v1, s2 = s1+v2, s3 = s2+v3;
        float t = s3;
#pragma unroll
        for (int o = 1; o < 32; o <<= 1) {
            float u2 = __shfl_up_sync(0xffffffffu, t, o);
            if (tid >= o) t += u2;
        }
        float base = t - s3;
        acum[tid*4+0] = -(base+v0); acum[tid*4+1] = -(base+s1);
        acum[tid*4+2] = -(base+s2); acum[tid*4+3] = -(base+s3);
    }
    __syncthreads();
    const float alast = acum[127];
    if (tid < 128) {
        darr[tid] = __expf(alast - acum[tid]);
        g_acum[(size_t)chunk_id * CHUNK_ + tid] = acum[tid];
    }
    if (tid == 0) g_dc[chunk_id] = __expf(alast);

#pragma unroll
    for (int pass = 0; pass < 8; pass++) {
        int r = pass * 16 + (tid >> 4);
        int col = (tid & 15) * 4;
        const float* row = g_xconv + (bt0 + r) * CONV_DIM;
        float4 cv = *(const float4*)(row + D_INNER + NQK*DSTATE + h*DSTATE + col);
        Ct[(col+0)*CTS + r] = cv.x; Ct[(col+1)*CTS + r] = cv.y;
        Ct[(col+2)*CTS + r] = cv.z; Ct[(col+3)*CTS + r] = cv.w;
        float4 bv = *(const float4*)(row + D_INNER + h*DSTATE + col);
        Btm[(col+0)*CTS + r] = bv.x; Btm[(col+1)*CTS + r] = bv.y;
        Btm[(col+2)*CTS + r] = bv.z; Btm[(col+3)*CTS + r] = bv.w;
    }
#pragma unroll
    for (int pass = 0; pass < 4; pass++) {
        int r = pass * 32 + (tid >> 3);
        int col = (tid & 7) * 4;
        float4 xv = *(const float4*)(g_xconv + (bt0 + r) * CONV_DIM + h*HEADDIM + col);
        Xs[r*XSS + col+0] = xv.x; Xs[r*XSS + col+1] = xv.y;
        Xs[r*XSS + col+2] = xv.z; Xs[r*XSS + col+3] = xv.w;
    }
    __syncthreads();

    // --- G = C.B^T (f32x2 accumulators) ---
    const int ty = tid >> 4, tx = tid & 15;
    unsigned long long acc2[8][4];
#pragma unroll
    for (int i = 0; i < 8; i++)
#pragma unroll
        for (int j = 0; j < 4; j++) acc2[i][j] = 0ull;
#pragma unroll 4
    for (int n = 0; n < 64; n++) {
        float4 a0 = *(const float4*)&Ct[n*CTS + ty*8];
        float4 a1 = *(const float4*)&Ct[n*CTS + ty*8 + 4];
        float4 b0 = *(const float4*)&Btm[n*CTS + tx*8];
        float4 b1 = *(const float4*)&Btm[n*CTS + tx*8 + 4];
        unsigned long long b2[4];
        b2[0] = packf2(b0.x, b0.y); b2[1] = packf2(b0.z, b0.w);
        b2[2] = packf2(b1.x, b1.y); b2[3] = packf2(b1.z, b1.w);
        float av[8] = {a0.x,a0.y,a0.z,a0.w,a1.x,a1.y,a1.z,a1.w};
#pragma unroll
        for (int i = 0; i < 8; i++) {
            unsigned long long a2 = packf2(av[i], av[i]);
#pragma unroll
            for (int j = 0; j < 4; j++) acc2[i][j] = ffma2(a2, b2[j], acc2[i][j]);
        }
    }
    float al[8], asv[8];
#pragma unroll
    for (int i = 0; i < 8; i++) al[i] = acum[ty*8 + i];
#pragma unroll
    for (int j = 0; j < 8; j++) asv[j] = acum[tx*8 + j];
#pragma unroll
    for (int i = 0; i < 8; i++) {
        int l = ty*8 + i;
        float g[8];
#pragma unroll
        for (int j = 0; j < 4; j++) {
            float2 v = unpackf2(acc2[i][j]);
            g[2*j] = v.x; g[2*j+1] = v.y;
        }
#pragma unroll
        for (int j = 0; j < 8; j++) {
            int s = tx*8 + j;
            g[j] = (s <= l) ? g[j] * __expf(al[i] - asv[j]) : 0.f;
        }
        *(float4*)&Ps[l*CTS + tx*8]     = make_float4(g[0],g[1],g[2],g[3]);
        *(float4*)&Ps[l*CTS + tx*8 + 4] = make_float4(g[4],g[5],g[6],g[7]);
    }
    __syncthreads();

    // --- Y_diag = P @ X (f32x2) ---
    {
        const int lq = tid >> 3, pq = tid & 7;
        unsigned long long yacc[4][2];
#pragma unroll
        for (int i = 0; i < 4; i++) { yacc[i][0] = 0ull; yacc[i][1] = 0ull; }
        for (int s = 0; s < 128; s++) {
            float bf0 = Xs[s*XSS + pq*4+0];
            float bf1 = Xs[s*XSS + pq*4+1];
            float bf2 = Xs[s*XSS + pq*4+2];
            float bf3 = Xs[s*XSS + pq*4+3];
            unsigned long long x0 = packf2(bf0, bf1);
            unsigned long long x1 = packf2(bf2, bf3);
#pragma unroll
            for (int i = 0; i < 4; i++) {
                float a = Ps[(lq*4+i)*CTS + s];
                unsigned long long a2 = packf2(a, a);
                yacc[i][0] = ffma2(a2, x0, yacc[i][0]);
                yacc[i][1] = ffma2(a2, x1, yacc[i][1]);
            }
        }
#pragma unroll
        for (int i = 0; i < 4; i++) {
            float2 v0 = unpackf2(yacc[i][0]);
            float2 v1 = unpackf2(yacc[i][1]);
            size_t row = (bt0 + lq*4 + i) * D_INNER + h*HEADDIM + pq*4;
            *(float4*)&g_y[row] = make_float4(v0.x, v0.y, v1.x, v1.y);
        }
    }

    // --- states[p][n] = sum_l B[l][n]*decay[l]*X[l][p] (f32x2) ---
    {
        const int n  = tid >> 2;
        const int pg = tid & 3;
        unsigned long long sacc[4];
#pragma unroll
        for (int j = 0; j < 4; j++) sacc[j] = 0ull;
        for (int l = 0; l < 128; l++) {
            float bv = Btm[n*CTS + l] * darr[l];
            unsigned long long b2 = packf2(bv, bv);
#pragma unroll
            for (int j = 0; j < 4; j++) {
                unsigned long long x2 = packf2(Xs[l*XSS + pg*8 + 2*j],
                                               Xs[l*XSS + pg*8 + 2*j + 1]);
                sacc[j] = ffma2(b2, x2, sacc[j]);
            }
        }
        size_t base = (size_t)chunk_id * (HEADDIM * DSTATE);
#pragma unroll
        for (int j = 0; j < 4; j++) {
            float2 v = unpackf2(sacc[j]);
            g_states[base + (size_t)(pg*8 + 2*j)     * DSTATE + n] = v.x;
            g_states[base + (size_t)(pg*8 + 2*j + 1) * DSTATE + n] = v.y;
        }
    }
}

// ---------------------------------------------------------------------------
__global__ void scan_kernel()
{
    const int bh = blockIdx.x;
    const int b = bh >> 5, h = bh & 31;
    const int e = threadIdx.x * 4;
    float4 S = make_float4(0.f,0.f,0.f,0.f);
    for (int c = 0; c < NC_; c++) {
        const int cid = (b * NC_ + c) * NV_ + h;
        size_t base = (size_t)cid * (HEADDIM * DSTATE) + e;
        *(float4*)&g_prevs[base] = S;
        float4 st = *(const float4*)&g_states[base];
        float d = g_dc[cid];
        S.x = S.x*d + st.x; S.y = S.y*d + st.y;
        S.z = S.z*d + st.z; S.w = S.w*d + st.w;
    }
}

// ---------------------------------------------------------------------------
// Y_off + D*x + SiLU gating; writes SPLIT-BF16 y directly (for out-proj).
// ---------------------------------------------------------------------------
__global__ __launch_bounds__(256) void yoff_kernel(
    const float* __restrict__ z_bias, const float* __restrict__ Dvec,
    __nv_bfloat16* __restrict__ yhi, __nv_bfloat16* __restrict__ ylo)
{
    __shared__ float Cs[128 * 65];
    __shared__ float Pv[32 * 65];
    __shared__ float ea[128];
    const int tid = threadIdx.x;
    const int h = blockIdx.x, c = blockIdx.y, b = blockIdx.z;
    const size_t bt0 = (size_t)b * SEQ + (size_t)c * CHUNK_;
    const int chunk_id = (b * NC_ + c) * NV_ + h;

    if (tid < 128) ea[tid] = __expf(g_acum[(size_t)chunk_id * CHUNK_ + tid]);
#pragma unroll
    for (int pass = 0; pass < 8; pass++) {
        int idx = pass * 256 + tid;
        int r = idx >> 4, col = (idx & 15) * 4;
        float4 v = *(const float4*)(g_xconv + (bt0 + r) * CONV_DIM
                                    + D_INNER + NQK*DSTATE + h*DSTATE + col);
        Cs[r*65 + col+0] = v.x; Cs[r*65 + col+1] = v.y;
        Cs[r*65 + col+2] = v.z; Cs[r*65 + col+3] = v.w;
    }
    size_t pbase = (size_t)chunk_id * (HEADDIM * DSTATE);
#pragma unroll
    for (int pass = 0; pass < 2; pass++) {
        int idx = pass * 256 + tid;
        int p = idx >> 4, col = (idx & 15) * 4;
        float4 v = *(const float4*)(g_prevs + pbase + (size_t)p * DSTATE + col);
        Pv[p*65 + col+0] = v.x; Pv[p*65 + col+1] = v.y;
        Pv[p*65 + col+2] = v.z; Pv[p*65 + col+3] = v.w;
    }
    __syncthreads();

    const int l = tid >> 1;
    const int p0 = (tid & 1) * 16;
    const float e = ea[l];
    unsigned long long acc2[8];
#pragma unroll
    for (int j = 0; j < 8; j++) acc2[j] = 0ull;
    for (int n = 0; n < 64; n++) {
        float cv = Cs[l*65 + n];
        unsigned long long c2 = packf2(cv, cv);
#pragma unroll
        for (int j = 0; j < 8; j++) {
            unsigned long long p2 = packf2(Pv[(p0 + 2*j)*65 + n],
                                           Pv[(p0 + 2*j + 1)*65 + n]);
            acc2[j] = ffma2(c2, p2, acc2[j]);
        }
    }
    float acc[16];
#pragma unroll
    for (int j = 0; j < 8; j++) {
        float2 v = unpackf2(acc2[j]);
        acc[2*j] = v.x; acc[2*j+1] = v.y;
    }
    const float Dh = Dvec[h];
#pragma unroll
    for (int j = 0; j < 16; j++) {
        int p = p0 + j;
        int ch = h * HEADDIM + p;
        size_t oidx = (bt0 + l) * D_INNER + ch;
        float x  = g_xconv[(bt0 + l) * CONV_DIM + ch];
        float zd = g_xbcza[(bt0 + l) * IN_PROJ + CONV_DIM + ch] + z_bias[ch];
        float sg = zd / (1.f + __expf(-zd));
        float yv = (g_y[oidx] + e * acc[j] + Dh * x) * sg;
        __nv_bfloat16 hb = __float2bfloat16(yv);
        yhi[oidx] = hb;
        ylo[oidx] = __float2bfloat16(yv - __bfloat162float(hb));
    }
}

// ---------------------------------------------------------------------------
extern "C" void kernel_launch(void* const* d_in, const int* in_sizes, int n_in,
                              void* d_out, int out_size)
{
    const float* u      = (const float*)d_in[0];
    const float* W_in   = (const float*)d_in[1];
    const float* conv_w = (const float*)d_in[2];
    const float* conv_b = (const float*)d_in[3];
    const float* z_bias = (const float*)d_in[4];
    const float* Dvec   = (const float*)d_in[5];
    const float* W_out  = (const float*)d_in[6];
    float* out = (float*)d_out;

    float *p_xbcza = nullptr;
    __nv_bfloat16 *p_ah, *p_al, *p_w1h, *p_w1l, *p_w2h, *p_w2l;
    cudaGetSymbolAddress((void**)&p_xbcza, g_xbcza);
    cudaGetSymbolAddress((void**)&p_ah, g_act_hi);
    cudaGetSymbolAddress((void**)&p_al, g_act_lo);
    cudaGetSymbolAddress((void**)&p_w1h, g_w1_hi);
    cudaGetSymbolAddress((void**)&p_w1l, g_w1_lo);
    cudaGetSymbolAddress((void**)&p_w2h, g_w2_hi);
    cudaGetSymbolAddress((void**)&p_w2l, g_w2_lo);

    static int attr_set = 0;
    if (!attr_set) {
        cudaFuncSetAttribute(gemm_hmma,
            cudaFuncAttributeMaxDynamicSharedMemorySize, GEMM_SMEM);
        size_t csm = (64*CTS + 64*CTS + 128*XSS + 128*CTS + 2*CHUNK_) * sizeof(float);
        cudaFuncSetAttribute(chunk_kernel,
            cudaFuncAttributeMaxDynamicSharedMemorySize, (int)csm);
        attr_set = 1;
    }

    // split conversions
    cvt_split<<<(BT*1024)/1024, 256>>>(u, p_ah, p_al, BT*1024, BT*1024);
    cvt_split<<<(IN_PROJ_PAD*1024)/1024, 256>>>(W_in, p_w1h, p_w1l,
                                                IN_PROJ*1024, IN_PROJ_PAD*1024);
    cvt_split<<<(1024*1024)/1024, 256>>>(W_out, p_w2h, p_w2l, 1024*1024, 1024*1024);

    // in-proj
    {
        dim3 grid(IN_PROJ_PAD / 128, BT / 128);
        gemm_hmma<<<grid, 256, GEMM_SMEM>>>(p_ah, p_al, p_w1h, p_w1l,
                                            p_xbcza, D_MODEL, IN_PROJ, IN_PROJ);
    }
    // conv
    {
        dim3 grid(CONV_DIM / CCH, BT / CTT);
        conv_kernel<<<grid, 256>>>(conv_w, conv_b);
    }
    // chunk
    {
        size_t csm = (64*CTS + 64*CTS + 128*XSS + 128*CTS + 2*CHUNK_) * sizeof(float);
        dim3 grid(NV_, NC_, BATCH);
        chunk_kernel<<<grid, 256, csm>>>();
    }
    scan_kernel<<<BATCH * NV_, 512>>>();
    // y_off + gating + fused split-bf16 output
    {
        dim3 grid(NV_, NC_, BATCH);
        yoff_kernel<<<grid, 256>>>(z_bias, Dvec, p_ah, p_al);
    }
    // out-proj (consumes yoff's split output directly)
    {
        dim3 grid(D_MODEL / 128, BT / 128);
        gemm_hmma<<<grid, 256, GEMM_SMEM>>>(p_ah, p_al, p_w2h, p_w2l,
                                            out, D_INNER, D_MODEL, D_MODEL);
    }
}

// round 9
// speedup vs baseline: 1.0804x; 1.0804x over previous
#include <cuda_runtime.h>
#include <cuda_bf16.h>
#include <cstdint>
#include <cstddef>

#define D_MODEL   1024
#define D_INNER   1024
#define NQK       32
#define NV_       32
#define DSTATE    64
#define DCONV     4
#define CHUNK_    128
#define CONV_DIM  5120
#define HEADDIM   32
#define IN_PROJ   6176
#define IN_PROJ_PAD 6272
#define BATCH     2
#define SEQ       8192
#define BT        16384
#define NC_       64

// ---- scratch (device globals) ----
__device__ __align__(16) float g_xbcza[(size_t)BT * IN_PROJ];
__device__ __align__(16) float g_xconv[(size_t)BT * CONV_DIM];
__device__ __align__(16) float g_y[(size_t)BT * D_INNER];
__device__ __align__(16) float g_states[(size_t)BATCH * NC_ * NV_ * HEADDIM * DSTATE];
__device__ __align__(16) float g_prevs [(size_t)BATCH * NC_ * NV_ * HEADDIM * DSTATE];
__device__ __align__(16) float g_acum  [(size_t)BATCH * NC_ * NV_ * CHUNK_];
__device__ __align__(16) float g_dc    [BATCH * NC_ * NV_];
__device__ __align__(16) __nv_bfloat16 g_act_hi[(size_t)BT * 1024];
__device__ __align__(16) __nv_bfloat16 g_act_lo[(size_t)BT * 1024];
__device__ __align__(16) __nv_bfloat16 g_w1_hi [(size_t)IN_PROJ_PAD * 1024];
__device__ __align__(16) __nv_bfloat16 g_w1_lo [(size_t)IN_PROJ_PAD * 1024];
__device__ __align__(16) __nv_bfloat16 g_w2_hi [(size_t)1024 * 1024];
__device__ __align__(16) __nv_bfloat16 g_w2_lo [(size_t)1024 * 1024];

// ===========================================================================
// split-bf16 conversion
// ===========================================================================
__global__ void cvt_split(const float* __restrict__ s,
                          __nv_bfloat16* __restrict__ hi,
                          __nv_bfloat16* __restrict__ lo,
                          int n_real, int n_total)
{
    int i = (blockIdx.x * 256 + threadIdx.x) * 4;
    if (i >= n_total) return;
    __nv_bfloat16 h[4], l[4];
    if (i < n_real) {
        float4 v = *(const float4*)(s + i);
        float a[4] = {v.x, v.y, v.z, v.w};
#pragma unroll
        for (int j = 0; j < 4; j++) {
            h[j] = __float2bfloat16(a[j]);
            l[j] = __float2bfloat16(a[j] - __bfloat162float(h[j]));
        }
    } else {
#pragma unroll
        for (int j = 0; j < 4; j++) { h[j] = __float2bfloat16(0.f); l[j] = h[j]; }
    }
    *(__nv_bfloat162*)(hi + i)     = __nv_bfloat162(h[0], h[1]);
    *(__nv_bfloat162*)(hi + i + 2) = __nv_bfloat162(h[2], h[3]);
    *(__nv_bfloat162*)(lo + i)     = __nv_bfloat162(l[0], l[1]);
    *(__nv_bfloat162*)(lo + i + 2) = __nv_bfloat162(l[2], l[3]);
}

// ===========================================================================
// HMMA split-bf16 GEMM (NT), cp.async 2-stage pipeline, 512 threads (16 warps)
// ===========================================================================
__device__ __forceinline__ uint32_t smem_u32(const void* p) {
    uint32_t a;
    asm("{ .reg .u64 t; cvta.to.shared.u64 t, %1; cvt.u32.u64 %0, t; }"
        : "=r"(a) : "l"(p));
    return a;
}
__device__ __forceinline__ uint32_t sw128(uint32_t off) {
    return off ^ ((off >> 3) & 0x70);
}
__device__ __forceinline__ void ldmat4(uint32_t& r0, uint32_t& r1,
                                       uint32_t& r2, uint32_t& r3, uint32_t a) {
    asm volatile("ldmatrix.sync.aligned.m8n8.x4.shared.b16 {%0,%1,%2,%3}, [%4];"
                 : "=r"(r0), "=r"(r1), "=r"(r2), "=r"(r3) : "r"(a));
}
__device__ __forceinline__ void mma16816(float* c, const uint32_t* a,
                                         uint32_t b0, uint32_t b1) {
    asm volatile(
        "mma.sync.aligned.m16n8k16.row.col.f32.bf16.bf16.f32 "
        "{%0,%1,%2,%3}, {%4,%5,%6,%7}, {%8,%9}, {%0,%1,%2,%3};"
        : "+f"(c[0]), "+f"(c[1]), "+f"(c[2]), "+f"(c[3])
        : "r"(a[0]), "r"(a[1]), "r"(a[2]), "r"(a[3]), "r"(b0), "r"(b1));
}
__device__ __forceinline__ void cp16(uint32_t dst, const void* src) {
    asm volatile("cp.async.cg.shared.global [%0], [%1], 16;"
                 :: "r"(dst), "l"(src));
}

// 512 threads: 1024 16B-units, 2 per thread
__device__ __forceinline__ void load_tile_async512(
    const __nv_bfloat16* __restrict__ g, int row0, int K, int k0,
    uint32_t sbase, int tid)
{
#pragma unroll
    for (int j = 0; j < 2; j++) {
        int u = tid + 512 * j;
        int row = u >> 3, cg = u & 7;
        uint32_t off = (uint32_t)(row * 128 + cg * 16);
        cp16(sbase + sw128(off), g + (size_t)(row0 + row) * K + k0 + cg * 8);
    }
}

#define STAGE_SZ 65536u
#define GEMM_SMEM (2 * 65536)
__global__ __launch_bounds__(512, 1)
void gemm_hmma(const __nv_bfloat16* __restrict__ Ahi,
               const __nv_bfloat16* __restrict__ Alo,
               const __nv_bfloat16* __restrict__ Bhi,
               const __nv_bfloat16* __restrict__ Blo,
               float* __restrict__ C, int K, int Nreal, int ldc)
{
    extern __shared__ char sm[];
    const uint32_t s0 = smem_u32(sm);
    const int tid = threadIdx.x;
    const int wid = tid >> 5, lid = tid & 31;
    const int wm = wid & 3, wn = wid >> 2;          // 4 x 4 warp grid, 32x32 tiles
    const int m0 = blockIdx.y * 128, n0 = blockIdx.x * 128;

    float acc[2][4][4];
#pragma unroll
    for (int i = 0; i < 2; i++)
#pragma unroll
        for (int j = 0; j < 4; j++)
#pragma unroll
            for (int q = 0; q < 4; q++) acc[i][j][q] = 0.f;

    const int lrow = lid & 15;
    const int lkb  = (lid >> 4) * 16;
    const int NKC = K >> 6;

    {
        uint32_t base = s0;
        load_tile_async512(Ahi, m0, K, 0, base,             tid);
        load_tile_async512(Alo, m0, K, 0, base + 16384,     tid);
        load_tile_async512(Bhi, n0, K, 0, base + 32768,     tid);
        load_tile_async512(Blo, n0, K, 0, base + 49152,     tid);
        asm volatile("cp.async.commit_group;");
    }

    for (int kc = 0; kc < NKC; kc++) {
        if (kc + 1 < NKC) {
            uint32_t base = s0 + ((kc + 1) & 1) * STAGE_SZ;
            int k0 = (kc + 1) << 6;
            load_tile_async512(Ahi, m0, K, k0, base,         tid);
            load_tile_async512(Alo, m0, K, k0, base + 16384, tid);
            load_tile_async512(Bhi, n0, K, k0, base + 32768, tid);
            load_tile_async512(Blo, n0, K, k0, base + 49152, tid);
            asm volatile("cp.async.commit_group;");
            asm volatile("cp.async.wait_group 1;");
        } else {
            asm volatile("cp.async.wait_group 0;");
        }
        __syncthreads();

        const uint32_t sAH = s0 + (kc & 1) * STAGE_SZ;
        const uint32_t sAL = sAH + 16384;
        const uint32_t sBH = sAH + 32768;
        const uint32_t sBL = sAH + 49152;
#pragma unroll
        for (int ks = 0; ks < 4; ks++) {
            const int kb = ks * 32 + lkb;
            uint32_t bh[2][4], bl[2][4];
#pragma unroll
            for (int g2 = 0; g2 < 2; g2++) {
                uint32_t off = (uint32_t)((wn * 32 + g2 * 16 + lrow) * 128 + kb);
                ldmat4(bh[g2][0], bh[g2][1], bh[g2][2], bh[g2][3], sBH + sw128(off));
                ldmat4(bl[g2][0], bl[g2][1], bl[g2][2], bl[g2][3], sBL + sw128(off));
            }
#pragma unroll
            for (int mi = 0; mi < 2; mi++) {
                uint32_t ah[4], al[4];
                uint32_t off = (uint32_t)((wm * 32 + mi * 16 + lrow) * 128 + kb);
                ldmat4(ah[0], ah[1], ah[2], ah[3], sAH + sw128(off));
                ldmat4(al[0], al[1], al[2], al[3], sAL + sw128(off));
#pragma unroll
                for (int ni = 0; ni < 4; ni++) {
                    const int g2 = ni >> 1, pt = ni & 1;
                    mma16816(acc[mi][ni], ah, bh[g2][pt], bh[g2][pt + 2]);
                    mma16816(acc[mi][ni], ah, bl[g2][pt], bl[g2][pt + 2]);
                    mma16816(acc[mi][ni], al, bh[g2][pt], bh[g2][pt + 2]);
                }
            }
        }
        __syncthreads();
    }

    const int crow = lid >> 2, ccol = (lid & 3) * 2;
#pragma unroll
    for (int mi = 0; mi < 2; mi++) {
#pragma unroll
        for (int ni = 0; ni < 4; ni++) {
            int n = n0 + wn * 32 + ni * 8 + ccol;
            if (n >= Nreal) continue;
            int m = m0 + wm * 32 + mi * 16 + crow;
            *(float2*)(C + (size_t)m * ldc + n) =
                make_float2(acc[mi][ni][0], acc[mi][ni][1]);
            *(float2*)(C + (size_t)(m + 8) * ldc + n) =
                make_float2(acc[mi][ni][2], acc[mi][ni][3]);
        }
    }
}

// ---------------------------------------------------------------------------
// Depthwise causal conv (4 taps) + bias — smem-tiled
// ---------------------------------------------------------------------------
#define CCH 64
#define CTT 64
__global__ __launch_bounds__(256) void conv_kernel(const float* __restrict__ cw,
                                                   const float* __restrict__ cb)
{
    __shared__ float s[(CTT + 3) * CCH];
    const int tid = threadIdx.x;
    const int c0 = blockIdx.x * CCH;
    const int tile = blockIdx.y;
    const int b = tile >> 7;
    const int t0 = (tile & 127) * CTT;
    const size_t row0 = (size_t)b * SEQ + t0;

    for (int e = tid; e < (CTT + 3) * CCH; e += 256) {
        int tl = e >> 6, c = e & 63;
        int t = t0 + tl - 3;
        float v = 0.f;
        if (t >= 0) v = g_xbcza[((size_t)b * SEQ + t) * IN_PROJ + c0 + c];
        s[e] = v;
    }
    __syncthreads();

    const int c = tid & 63, trow = tid >> 6;
    const int ch = c0 + c;
    const float w0 = cw[ch * 4 + 0], w1 = cw[ch * 4 + 1];
    const float w2 = cw[ch * 4 + 2], w3 = cw[ch * 4 + 3];
    const float bia = cb[ch];
#pragma unroll
    for (int j = 0; j < 16; j++) {
        int tl = trow + 4 * j;
        float acc = bia
            + w0 * s[(tl + 0) * CCH + c]
            + w1 * s[(tl + 1) * CCH + c]
            + w2 * s[(tl + 2) * CCH + c]
            + w3 * s[(tl + 3) * CCH + c];
        g_xconv[(row0 + tl) * CONV_DIM + ch] = acc;
    }
}

// ---------------------------------------------------------------------------
// Chunk kernel (R7 scalar version): per (h, c, b). dyn smem 153,088 B.
// ---------------------------------------------------------------------------
#define CTS 132
#define XSS 33
__global__ __launch_bounds__(256, 1) void chunk_kernel()
{
    extern __shared__ float smf[];
    float* Ct   = smf;
    float* Btm  = Ct + 64 * CTS;
    float* Xs   = Btm + 64 * CTS;
    float* Ps   = Xs + 128 * XSS;
    float* acum = Ps + 128 * CTS;
    float* darr = acum + CHUNK_;

    const int tid = threadIdx.x;
    const int h = blockIdx.x, c = blockIdx.y, b = blockIdx.z;
    const size_t bt0 = (size_t)b * SEQ + (size_t)c * CHUNK_;
    const int chunk_id = (b * NC_ + c) * NV_ + h;

    if (tid < 128) {
        float a = g_xbcza[(bt0 + tid) * IN_PROJ + (CONV_DIM + D_INNER) + h];
        darr[tid] = (a > 20.f) ? a : log1pf(expf(a));
    }
    __syncthreads();
    if (tid < 32) {
        float v0 = darr[tid*4+0], v1 = darr[tid*4+1];
        float v2 = darr[tid*4+2], v3 = darr[tid*4+3];
        float s1 = v0+v1, s2 = s1+v2, s3 = s2+v3;
        float t = s3;
#pragma unroll
        for (int o = 1; o < 32; o <<= 1) {
            float u2 = __shfl_up_sync(0xffffffffu, t, o);
            if (tid >= o) t += u2;
        }
        float base = t - s3;
        acum[tid*4+0] = -(base+v0); acum[tid*4+1] = -(base+s1);
        acum[tid*4+2] = -(base+s2); acum[tid*4+3] = -(base+s3);
    }
    __syncthreads();
    const float alast = acum[127];
    if (tid < 128) {
        darr[tid] = __expf(alast - acum[tid]);
        g_acum[(size_t)chunk_id * CHUNK_ + tid] = acum[tid];
    }
    if (tid == 0) g_dc[chunk_id] = __expf(alast);

#pragma unroll
    for (int pass = 0; pass < 8; pass++) {
        int r = pass * 16 + (tid >> 4);
        int col = (tid & 15) * 4;
        const float* row = g_xconv + (bt0 + r) * CONV_DIM;
        float4 cv = *(const float4*)(row + D_INNER + NQK*DSTATE + h*DSTATE + col);
        Ct[(col+0)*CTS + r] = cv.x; Ct[(col+1)*CTS + r] = cv.y;
        Ct[(col+2)*CTS + r] = cv.z; Ct[(col+3)*CTS + r] = cv.w;
        float4 bv = *(const float4*)(row + D_INNER + h*DSTATE + col);
        Btm[(col+0)*CTS + r] = bv.x; Btm[(col+1)*CTS + r] = bv.y;
        Btm[(col+2)*CTS + r] = bv.z; Btm[(col+3)*CTS + r] = bv.w;
    }
#pragma unroll
    for (int pass = 0; pass < 4; pass++) {
        int r = pass * 32 + (tid >> 3);
        int col = (tid & 7) * 4;
        float4 xv = *(const float4*)(g_xconv + (bt0 + r) * CONV_DIM + h*HEADDIM + col);
        Xs[r*XSS + col+0] = xv.x; Xs[r*XSS + col+1] = xv.y;
        Xs[r*XSS + col+2] = xv.z; Xs[r*XSS + col+3] = xv.w;
    }
    __syncthreads();

    const int ty = tid >> 4, tx = tid & 15;
    float accG[8][8];
#pragma unroll
    for (int i = 0; i < 8; i++)
#pragma unroll
        for (int j = 0; j < 8; j++) accG[i][j] = 0.f;
#pragma unroll 4
    for (int n = 0; n < 64; n++) {
        float4 a0 = *(const float4*)&Ct[n*CTS + ty*8];
        float4 a1 = *(const float4*)&Ct[n*CTS + ty*8 + 4];
        float4 b0 = *(const float4*)&Btm[n*CTS + tx*8];
        float4 b1 = *(const float4*)&Btm[n*CTS + tx*8 + 4];
        float av[8] = {a0.x,a0.y,a0.z,a0.w,a1.x,a1.y,a1.z,a1.w};
        float bv[8] = {b0.x,b0.y,b0.z,b0.w,b1.x,b1.y,b1.z,b1.w};
#pragma unroll
        for (int i = 0; i < 8; i++)
#pragma unroll
            for (int j = 0; j < 8; j++) accG[i][j] += av[i] * bv[j];
    }
    float al[8], asv[8];
#pragma unroll
    for (int i = 0; i < 8; i++) al[i] = acum[ty*8 + i];
#pragma unroll
    for (int j = 0; j < 8; j++) asv[j] = acum[tx*8 + j];
#pragma unroll
    for (int i = 0; i < 8; i++) {
        int l = ty*8 + i;
#pragma unroll
        for (int j = 0; j < 8; j++) {
            int s = tx*8 + j;
            accG[i][j] = (s <= l) ? accG[i][j] * __expf(al[i] - asv[j]) : 0.f;
        }
        *(float4*)&Ps[l*CTS + tx*8]     = make_float4(accG[i][0],accG[i][1],accG[i][2],accG[i][3]);
        *(float4*)&Ps[l*CTS + tx*8 + 4] = make_float4(accG[i][4],accG[i][5],accG[i][6],accG[i][7]);
    }
    __syncthreads();

    {
        const int lq = tid >> 3, pq = tid & 7;
        float acc[4][4] = {};
        for (int s = 0; s < 128; s++) {
            float bf0 = Xs[s*XSS + pq*4+0];
            float bf1 = Xs[s*XSS + pq*4+1];
            float bf2 = Xs[s*XSS + pq*4+2];
            float bf3 = Xs[s*XSS + pq*4+3];
#pragma unroll
            for (int i = 0; i < 4; i++) {
                float a = Ps[(lq*4+i)*CTS + s];
                acc[i][0] += a*bf0; acc[i][1] += a*bf1;
                acc[i][2] += a*bf2; acc[i][3] += a*bf3;
            }
        }
#pragma unroll
        for (int i = 0; i < 4; i++) {
            size_t row = (bt0 + lq*4 + i) * D_INNER + h*HEADDIM + pq*4;
            *(float4*)&g_y[row] = make_float4(acc[i][0],acc[i][1],acc[i][2],acc[i][3]);
        }
    }

    {
        const int n  = tid >> 2;
        const int pg = tid & 3;
        float acc[8] = {};
        for (int l = 0; l < 128; l++) {
            float bv = Btm[n*CTS + l] * darr[l];
#pragma unroll
            for (int j = 0; j < 8; j++) acc[j] += bv * Xs[l*XSS + pg*8 + j];
        }
        size_t base = (size_t)chunk_id * (HEADDIM * DSTATE);
#pragma unroll
        for (int j = 0; j < 8; j++)
            g_states[base + (size_t)(pg*8 + j) * DSTATE + n] = acc[j];
    }
}

// ---------------------------------------------------------------------------
__global__ void scan_kernel()
{
    const int bh = blockIdx.x;
    const int b = bh >> 5, h = bh & 31;
    const int e = threadIdx.x * 4;
    float4 S = make_float4(0.f,0.f,0.f,0.f);
    for (int c = 0; c < NC_; c++) {
        const int cid = (b * NC_ + c) * NV_ + h;
        size_t base = (size_t)cid * (HEADDIM * DSTATE) + e;
        *(float4*)&g_prevs[base] = S;
        float4 st = *(const float4*)&g_states[base];
        float d = g_dc[cid];
        S.x = S.x*d + st.x; S.y = S.y*d + st.y;
        S.z = S.z*d + st.z; S.w = S.w*d + st.w;
    }
}

// ---------------------------------------------------------------------------
// Y_off + D*x + SiLU gating (R7 scalar version).
// ---------------------------------------------------------------------------
__global__ __launch_bounds__(256) void yoff_kernel(
    const float* __restrict__ z_bias, const float* __restrict__ Dvec)
{
    __shared__ float Cs[128 * 65];
    __shared__ float Pv[32 * 65];
    __shared__ float ea[128];
    const int tid = threadIdx.x;
    const int h = blockIdx.x, c = blockIdx.y, b = blockIdx.z;
    const size_t bt0 = (size_t)b * SEQ + (size_t)c * CHUNK_;
    const int chunk_id = (b * NC_ + c) * NV_ + h;

    if (tid < 128) ea[tid] = __expf(g_acum[(size_t)chunk_id * CHUNK_ + tid]);
#pragma unroll
    for (int pass = 0; pass < 8; pass++) {
        int idx = pass * 256 + tid;
        int r = idx >> 4, col = (idx & 15) * 4;
        float4 v = *(const float4*)(g_xconv + (bt0 + r) * CONV_DIM
                                    + D_INNER + NQK*DSTATE + h*DSTATE + col);
        Cs[r*65 + col+0] = v.x; Cs[r*65 + col+1] = v.y;
        Cs[r*65 + col+2] = v.z; Cs[r*65 + col+3] = v.w;
    }
    size_t pbase = (size_t)chunk_id * (HEADDIM * DSTATE);
#pragma unroll
    for (int pass = 0; pass < 2; pass++) {
        int idx = pass * 256 + tid;
        int p = idx >> 4, col = (idx & 15) * 4;
        float4 v = *(const float4*)(g_prevs + pbase + (size_t)p * DSTATE + col);
        Pv[p*65 + col+0] = v.x; Pv[p*65 + col+1] = v.y;
        Pv[p*65 + col+2] = v.z; Pv[p*65 + col+3] = v.w;
    }
    __syncthreads();

    const int l = tid >> 1;
    const int p0 = (tid & 1) * 16;
    const float e = ea[l];
    float acc[16];
#pragma unroll
    for (int j = 0; j < 16; j++) acc[j] = 0.f;
    for (int n = 0; n < 64; n++) {
        float cv = Cs[l*65 + n];
#pragma unroll
        for (int j = 0; j < 16; j++) acc[j] += cv * Pv[(p0+j)*65 + n];
    }
    const float Dh = Dvec[h];
#pragma unroll
    for (int j = 0; j < 16; j++) {
        int p = p0 + j;
        int ch = h * HEADDIM + p;
        size_t oidx = (bt0 + l) * D_INNER + ch;
        float x  = g_xconv[(bt0 + l) * CONV_DIM + ch];
        float zd = g_xbcza[(bt0 + l) * IN_PROJ + CONV_DIM + ch] + z_bias[ch];
        float sg = zd / (1.f + __expf(-zd));
        g_y[oidx] = (g_y[oidx] + e * acc[j] + Dh * x) * sg;
    }
}

// ---------------------------------------------------------------------------
extern "C" void kernel_launch(void* const* d_in, const int* in_sizes, int n_in,
                              void* d_out, int out_size)
{
    const float* u      = (const float*)d_in[0];
    const float* W_in   = (const float*)d_in[1];
    const float* conv_w = (const float*)d_in[2];
    const float* conv_b = (const float*)d_in[3];
    const float* z_bias = (const float*)d_in[4];
    const float* Dvec   = (const float*)d_in[5];
    const float* W_out  = (const float*)d_in[6];
    float* out = (float*)d_out;

    float *p_xbcza = nullptr, *p_y = nullptr;
    __nv_bfloat16 *p_ah, *p_al, *p_w1h, *p_w1l, *p_w2h, *p_w2l;
    cudaGetSymbolAddress((void**)&p_xbcza, g_xbcza);
    cudaGetSymbolAddress((void**)&p_y, g_y);
    cudaGetSymbolAddress((void**)&p_ah, g_act_hi);
    cudaGetSymbolAddress((void**)&p_al, g_act_lo);
    cudaGetSymbolAddress((void**)&p_w1h, g_w1_hi);
    cudaGetSymbolAddress((void**)&p_w1l, g_w1_lo);
    cudaGetSymbolAddress((void**)&p_w2h, g_w2_hi);
    cudaGetSymbolAddress((void**)&p_w2l, g_w2_lo);

    static int attr_set = 0;
    if (!attr_set) {
        cudaFuncSetAttribute(gemm_hmma,
            cudaFuncAttributeMaxDynamicSharedMemorySize, GEMM_SMEM);
        size_t csm = (64*CTS + 64*CTS + 128*XSS + 128*CTS + 2*CHUNK_) * sizeof(float);
        cudaFuncSetAttribute(chunk_kernel,
            cudaFuncAttributeMaxDynamicSharedMemorySize, (int)csm);
        attr_set = 1;
    }

    // split conversions
    cvt_split<<<(BT*1024)/1024, 256>>>(u, p_ah, p_al, BT*1024, BT*1024);
    cvt_split<<<(IN_PROJ_PAD*1024)/1024, 256>>>(W_in, p_w1h, p_w1l,
                                                IN_PROJ*1024, IN_PROJ_PAD*1024);
    cvt_split<<<(1024*1024)/1024, 256>>>(W_out, p_w2h, p_w2l, 1024*1024, 1024*1024);

    // in-proj
    {
        dim3 grid(IN_PROJ_PAD / 128, BT / 128);
        gemm_hmma<<<grid, 512, GEMM_SMEM>>>(p_ah, p_al, p_w1h, p_w1l,
                                            p_xbcza, D_MODEL, IN_PROJ, IN_PROJ);
    }
    // conv
    {
        dim3 grid(CONV_DIM / CCH, BT / CTT);
        conv_kernel<<<grid, 256>>>(conv_w, conv_b);
    }
    // chunk
    {
        size_t csm = (64*CTS + 64*CTS + 128*XSS + 128*CTS + 2*CHUNK_) * sizeof(float);
        dim3 grid(NV_, NC_, BATCH);
        chunk_kernel<<<grid, 256, csm>>>();
    }
    scan_kernel<<<BATCH * NV_, 512>>>();
    {
        dim3 grid(NV_, NC_, BATCH);
        yoff_kernel<<<grid, 256>>>(z_bias, Dvec);
    }
    // out-proj
    cvt_split<<<(BT*1024)/1024, 256>>>(p_y, p_ah, p_al, BT*1024, BT*1024);
    {
        dim3 grid(D_MODEL / 128, BT / 128);
        gemm_hmma<<<grid, 512, GEMM_SMEM>>>(p_ah, p_al, p_w2h, p_w2l,
                                            out, D_INNER, D_MODEL, D_MODEL);
    }
}